// round 10
// baseline (speedup 1.0000x reference)
#include <cuda_runtime.h>
#include <cuda_bf16.h>
#include <math.h>
#include <stdint.h>

// ---------------- problem constants ----------------
#define CDIM   96
#define DD     32
#define HH     64
#define WWD    64
#define BATCH  2
#define SP     131072
#define NTOK   (BATCH * SP)
#define NWIN   2048
#define NHEAD  4
#define HDIM   24
#define NWT    64

// ---------------- device scratch ----------------
__device__ __nv_bfloat16 g_qkv [(size_t)NTOK * 3 * CDIM];  // window-token-major (q pre-scaled)
__device__ __nv_bfloat16 g_att [(size_t)NTOK * CDIM];      // window-token-major
__device__ float         g_x2  [(size_t)NTOK * CDIM];      // residual, SPATIAL token-major
__device__ __nv_bfloat16 g_hn  [(size_t)NTOK * CDIM];      // LN2 out, SPATIAL token-major
__device__ __nv_bfloat16 g_m1  [(size_t)NTOK * 4 * CDIM];  // fc1+gelu
__device__ uint32_t      g_biasF[8192];                    // fragment-ordered bias table
// bf16 weights
__device__ __nv_bfloat16 g_wqkv[288 * 96];
__device__ __nv_bfloat16 g_wproj[96 * 96];
__device__ __nv_bfloat16 g_wfc1[384 * 96];
__device__ __nv_bfloat16 g_wfc2[96 * 384];

__device__ __forceinline__ uint32_t packbf(float a, float b) {
    __nv_bfloat162 h = __floats2bfloat162_rn(a, b);
    return *reinterpret_cast<uint32_t*>(&h);
}
__device__ __forceinline__ float2 unpackbf(uint32_t u) {
    return __bfloat1622float2(*reinterpret_cast<const __nv_bfloat162*>(&u));
}

__global__ void k_wconv(const float* __restrict__ a, const float* __restrict__ b,
                        const float* __restrict__ c, const float* __restrict__ d)
{
    int i = blockIdx.x * 256 + threadIdx.x;
    if (i < 27648)            g_wqkv[i]          = __float2bfloat16_rn(a[i]);
    else if (i < 36864)       g_wproj[i - 27648] = __float2bfloat16_rn(b[i - 27648]);
    else if (i < 73728)       g_wfc1[i - 36864]  = __float2bfloat16_rn(c[i - 36864]);
    else if (i < 110592)      g_wfc2[i - 73728]  = __float2bfloat16_rn(d[i - 73728]);
}

// Precompute rel-pos bias table in mma-fragment order:
// addr = ((h*8 + (r>>4)*2 + ((r>>3)&1))*8 + nt)*32 + (r&7)*4 + t4
// value = packbf(bias(h,r,8nt+2t4), bias(h,r,8nt+2t4+1))
__global__ void k_bias(const float* __restrict__ rpb)
{
    int idx = blockIdx.x * 256 + threadIdx.x;   // 8192
    int t4 = idx & 3;
    int nt = (idx >> 2) & 7;
    int r  = (idx >> 5) & 63;
    int h  = idx >> 11;
    int j0 = nt * 8 + t4 * 2;
    int id = r >> 4, ih = (r >> 2) & 3, iw = r & 3;
    auto relf = [&](int j) {
        int jd = j >> 4, jh = (j >> 2) & 3, jw = j & 3;
        return (id - jd + 3) * 49 + (ih - jh + 3) * 7 + (iw - jw + 3);
    };
    float b0 = rpb[relf(j0) * NHEAD + h];
    float b1 = rpb[relf(j0 + 1) * NHEAD + h];
    uint32_t addr = (uint32_t)(((h * 8 + (r >> 4) * 2 + ((r >> 3) & 1)) * 8 + nt) * 32
                               + (r & 7) * 4 + t4);
    g_biasF[addr] = packbf(b0, b1);
}

// ---------------- mma helpers ----------------
#define PITCH 52

__device__ __forceinline__ void mma_bf16(float c[4], const uint32_t a[4], const uint32_t b[2]) {
    asm volatile(
        "mma.sync.aligned.m16n8k16.row.col.f32.bf16.bf16.f32 "
        "{%0,%1,%2,%3}, {%4,%5,%6,%7}, {%8,%9}, {%0,%1,%2,%3};\n"
        : "+f"(c[0]), "+f"(c[1]), "+f"(c[2]), "+f"(c[3])
        : "r"(a[0]), "r"(a[1]), "r"(a[2]), "r"(a[3]), "r"(b[0]), "r"(b[1]));
}

__device__ __forceinline__ void mma_tile96(const uint32_t* As, const uint32_t* Bs,
                                           float acc[2][6][4], int g, int t4, int wm, int wn)
{
    #pragma unroll
    for (int ks = 0; ks < 6; ks++) {
        int k8 = ks * 8;
        uint32_t af[2][4];
        #pragma unroll
        for (int mt = 0; mt < 2; mt++) {
            int rb = wm * 32 + mt * 16;
            af[mt][0] = As[(rb + g    ) * PITCH + k8 + t4    ];
            af[mt][1] = As[(rb + g + 8) * PITCH + k8 + t4    ];
            af[mt][2] = As[(rb + g    ) * PITCH + k8 + t4 + 4];
            af[mt][3] = As[(rb + g + 8) * PITCH + k8 + t4 + 4];
        }
        uint32_t bf[6][2];
        #pragma unroll
        for (int nt = 0; nt < 6; nt++) {
            int nb = wn * 48 + nt * 8;
            bf[nt][0] = Bs[(nb + g) * PITCH + k8 + t4    ];
            bf[nt][1] = Bs[(nb + g) * PITCH + k8 + t4 + 4];
        }
        #pragma unroll
        for (int mt = 0; mt < 2; mt++)
            #pragma unroll
            for (int nt = 0; nt < 6; nt++)
                mma_bf16(acc[mt][nt], af[mt], bf[nt]);
    }
}

__device__ __forceinline__ void stage_A96(const __nv_bfloat16* A, size_t bm, uint32_t* As, int tid) {
    for (int i = tid; i < 128 * 12; i += 256) {
        int row = i / 12, q = i - row * 12;
        ((uint4*)&As[row * PITCH])[q] = ((const uint4*)(A + (bm + row) * 96))[q];
    }
}
__device__ __forceinline__ void stage_B96(const __nv_bfloat16* Wb, int bn, uint32_t* Bs, int tid) {
    for (int i = tid; i < 96 * 12; i += 256) {
        int row = i / 12, q = i - row * 12;
        ((uint4*)&Bs[row * PITCH])[q] = ((const uint4*)(Wb + (size_t)(bn + row) * 96))[q];
    }
}

__device__ __forceinline__ void decode_tok(int r, int& b, int& d, int& h, int& w) {
    int widx = r >> 6, inner = r & 63;
    b = widx >> 11;
    int wi = widx & 2047;
    int wd = wi >> 8, wh = (wi >> 4) & 15, ww = wi & 15;
    int id = inner >> 4, ih = (inner >> 2) & 3, iw = inner & 3;
    d = (wd * 4 + id + 2) & 31;
    h = (wh * 4 + ih + 2) & 63;
    w = (ww * 4 + iw + 2) & 63;
}

// ============================================================
// K1: fused LN1 + roll + window + qkv GEMM. q output pre-scaled by 24^-0.5.
// ============================================================
__global__ void __launch_bounds__(256)
k_qkv(const float* __restrict__ x, const float* __restrict__ gw,
      const float* __restrict__ gb, const float* __restrict__ qbias)
{
    extern __shared__ char smem[];
    uint32_t* As = (uint32_t*)smem;
    uint32_t* Bs = (uint32_t*)(smem + 26624);
    float* sgw = (float*)(smem + 46592);
    float* sgb = sgw + 96;

    int tid = threadIdx.x;
    if (tid < 96) { sgw[tid] = gw[tid]; sgb[tid] = gb[tid]; }

    size_t bm = (size_t)blockIdx.x * 128;
    int t = tid & 127;
    int b, d, h, w;
    decode_tok((int)bm + t, b, d, h, w);
    size_t xbase = ((size_t)b * 96) * SP + (size_t)d * 4096 + h * 64 + w;
    int c0 = tid >> 7;

    for (int p = c0; p < 48; p += 2) {
        float v0 = x[xbase + (size_t)(2 * p) * SP];
        float v1 = x[xbase + (size_t)(2 * p + 1) * SP];
        As[t * PITCH + p] = packbf(v0, v1);
    }
    __syncthreads();

    if (tid < 128) {
        uint32_t* row = As + tid * PITCH;
        float s = 0.f, ss = 0.f;
        #pragma unroll
        for (int p = 0; p < 48; p++) {
            float2 f = unpackbf(row[p]);
            s += f.x + f.y; ss += f.x * f.x + f.y * f.y;
        }
        float mean = s * (1.f / 96.f);
        float rstd = rsqrtf(ss * (1.f / 96.f) - mean * mean + 1e-5f);
        #pragma unroll
        for (int p = 0; p < 48; p++) {
            float2 f = unpackbf(row[p]);
            f.x = (f.x - mean) * rstd * sgw[2 * p] + sgb[2 * p];
            f.y = (f.y - mean) * rstd * sgw[2 * p + 1] + sgb[2 * p + 1];
            row[p] = packbf(f.x, f.y);
        }
    }
    __syncthreads();

    int warp = tid >> 5, lane = tid & 31, g = lane >> 2, t4 = lane & 3;
    int wm = warp >> 1, wn = warp & 1;

    for (int bt = 0; bt < 3; bt++) {
        stage_B96(g_wqkv, bt * 96, Bs, tid);
        __syncthreads();
        float acc[2][6][4];
        #pragma unroll
        for (int i = 0; i < 2; i++)
            #pragma unroll
            for (int j = 0; j < 6; j++)
                #pragma unroll
                for (int r = 0; r < 4; r++) acc[i][j][r] = 0.f;
        mma_tile96(As, Bs, acc, g, t4, wm, wn);
        float scale = (bt == 0) ? 0.2041241452319315f : 1.0f;
        #pragma unroll
        for (int mt = 0; mt < 2; mt++)
            #pragma unroll
            for (int nt = 0; nt < 6; nt++) {
                int ncol = wn * 48 + nt * 8 + t4 * 2;
                #pragma unroll
                for (int half = 0; half < 2; half++) {
                    size_t row = bm + wm * 32 + mt * 16 + g + half * 8;
                    float v0 = (acc[mt][nt][half * 2 + 0] + qbias[bt * 96 + ncol]) * scale;
                    float v1 = (acc[mt][nt][half * 2 + 1] + qbias[bt * 96 + ncol + 1]) * scale;
                    *(uint32_t*)&g_qkv[row * 288 + bt * 96 + ncol] = packbf(v0, v1);
                }
            }
        __syncthreads();
    }
}

// ============================================================
// K2: tensor-core windowed attention. 512 thr = 16 warps:
// warp w -> head w>>2, row slab (w&3)*16. S=Q@K^T via mma,
// softmax in fragments, PV via mma (S frags -> A frags directly).
// ============================================================
// smem u32 offsets
#define AT_QS   0
#define AT_KS   5120
#define AT_VT   10240        // bf16 view, 4*24 rows * 36 u32 pitch
#define AT_BF   13696
#define AT_GT   21888
#define AT_SIZE (21952 * 4)  // 87808 B

__global__ void __launch_bounds__(512)
k_attn()
{
    extern __shared__ uint32_t sm[];
    uint32_t* Qs = sm + AT_QS;
    uint32_t* Ks = sm + AT_KS;
    uint32_t* VtU = sm + AT_VT;
    __nv_bfloat16* Vt = (__nv_bfloat16*)(sm + AT_VT);
    uint32_t* bF = sm + AT_BF;
    int* gtk = (int*)(sm + AT_GT);

    int tid = threadIdx.x;
    int bn  = blockIdx.x;
    int wi  = bn & (NWIN - 1);
    int wd = wi >> 8, wh = (wi >> 4) & 15, ww = wi & 15;
    bool interior = (wd != 7) && (wh != 15) && (ww != 15);

    const uint4* src4 = (const uint4*)(g_qkv + (size_t)bn * NWT * 288);
    const uint32_t* srcU = (const uint32_t*)src4;

    // Q/K staging: 1536 uint4 (sec,h,r,q)
    for (int i = tid; i < 1536; i += 512) {
        int sec = i / 768, rem = i - sec * 768;
        int h = rem / 192;
        int r2 = rem - h * 192;
        int r = r2 / 3, q = r2 - r * 3;
        uint4 v = src4[r * 36 + sec * 12 + h * 3 + q];
        uint32_t* dst = (sec ? Ks : Qs) + (h * 64 + r) * 20 + q * 4;
        *(uint4*)dst = v;
    }
    // zero pad cols 12..15 of Q/K rows
    for (int i = tid; i < 512; i += 512) {
        int sec = i >> 8, hr = i & 255;
        uint32_t* dst = (sec ? Ks : Qs) + hr * 20 + 12;
        *(uint4*)dst = make_uint4(0, 0, 0, 0);
    }
    // V transpose: (h, j, p) -> Vt[(h*24+2p)(+1)][j]
    for (int i = tid; i < 3072; i += 512) {
        int h = i / 768;
        int rem = i - h * 768;
        int j = rem / 12, p = rem - j * 12;
        uint32_t v = srcU[j * 144 + 96 + h * 12 + p];
        __nv_bfloat162 bv = *reinterpret_cast<__nv_bfloat162*>(&v);
        Vt[(h * 24 + 2 * p    ) * 72 + j] = bv.x;
        Vt[(h * 24 + 2 * p + 1) * 72 + j] = bv.y;
    }
    // bias table
    {
        const uint4* gb4 = (const uint4*)g_biasF;
        uint4* sb4 = (uint4*)bF;
        for (int i = tid; i < 2048; i += 512) sb4[i] = gb4[i];
    }
    // group ids
    if (tid < 64) {
        int id = tid >> 4, ih = (tid >> 2) & 3, iw = tid & 3;
        int da = wd * 4 + id, ha = wh * 4 + ih, wa = ww * 4 + iw;
        int rd = (da < DD  - 4) ? 0 : ((da < DD  - 2) ? 1 : 2);
        int rh = (ha < HH  - 4) ? 0 : ((ha < HH  - 2) ? 1 : 2);
        int rw = (wa < WWD - 4) ? 0 : ((wa < WWD - 2) ? 1 : 2);
        gtk[tid] = rd * 9 + rh * 3 + rw;
    }
    __syncthreads();

    int w = tid >> 5, lane = tid & 31;
    int g = lane >> 2, t4 = lane & 3;
    int h  = w >> 2;          // head
    int rq = w & 3;           // 16-row slab
    const uint32_t* Qh = Qs + h * 1280;
    const uint32_t* Kh = Ks + h * 1280;

    // ---- S = Q @ K^T  (m16 x n64, k=32 padded)
    float acc[8][4];
    #pragma unroll
    for (int nt = 0; nt < 8; nt++)
        #pragma unroll
        for (int r = 0; r < 4; r++) acc[nt][r] = 0.f;

    #pragma unroll
    for (int ks = 0; ks < 2; ks++) {
        uint32_t a[4];
        a[0] = Qh[(rq * 16 + g    ) * 20 + ks * 8 + t4    ];
        a[1] = Qh[(rq * 16 + g + 8) * 20 + ks * 8 + t4    ];
        a[2] = Qh[(rq * 16 + g    ) * 20 + ks * 8 + t4 + 4];
        a[3] = Qh[(rq * 16 + g + 8) * 20 + ks * 8 + t4 + 4];
        #pragma unroll
        for (int nt = 0; nt < 8; nt++) {
            uint32_t b[2];
            b[0] = Kh[(nt * 8 + g) * 20 + ks * 8 + t4    ];
            b[1] = Kh[(nt * 8 + g) * 20 + ks * 8 + t4 + 4];
            mma_bf16(acc[nt], a, b);
        }
    }

    // ---- softmax in fragments (unnormalized)
    int r0 = rq * 16 + g;
    int r1 = r0 + 8;
    float sum0 = 0.f, sum1 = 0.f;
    int base0 = ((h * 8 + rq * 2 + 0) * 8) * 32 + lane;
    int base1 = ((h * 8 + rq * 2 + 1) * 8) * 32 + lane;

    if (interior) {
        #pragma unroll
        for (int nt = 0; nt < 8; nt++) {
            float2 f0 = unpackbf(bF[base0 + nt * 32]);
            float2 f1 = unpackbf(bF[base1 + nt * 32]);
            float e0 = __expf(acc[nt][0] + f0.x);
            float e1 = __expf(acc[nt][1] + f0.y);
            float e2 = __expf(acc[nt][2] + f1.x);
            float e3 = __expf(acc[nt][3] + f1.y);
            acc[nt][0] = e0; acc[nt][1] = e1; acc[nt][2] = e2; acc[nt][3] = e3;
            sum0 += e0 + e1; sum1 += e2 + e3;
        }
    } else {
        int rg0 = gtk[r0], rg1 = gtk[r1];
        #pragma unroll
        for (int nt = 0; nt < 8; nt++) {
            int cA = nt * 8 + t4 * 2;
            int m0 = gtk[cA], m1 = gtk[cA + 1];
            float2 f0 = unpackbf(bF[base0 + nt * 32]);
            float2 f1 = unpackbf(bF[base1 + nt * 32]);
            float e0 = (m0 == rg0) ? __expf(acc[nt][0] + f0.x) : 0.f;
            float e1 = (m1 == rg0) ? __expf(acc[nt][1] + f0.y) : 0.f;
            float e2 = (m0 == rg1) ? __expf(acc[nt][2] + f1.x) : 0.f;
            float e3 = (m1 == rg1) ? __expf(acc[nt][3] + f1.y) : 0.f;
            acc[nt][0] = e0; acc[nt][1] = e1; acc[nt][2] = e2; acc[nt][3] = e3;
            sum0 += e0 + e1; sum1 += e2 + e3;
        }
    }
    sum0 += __shfl_xor_sync(0xffffffff, sum0, 1);
    sum0 += __shfl_xor_sync(0xffffffff, sum0, 2);
    sum1 += __shfl_xor_sync(0xffffffff, sum1, 1);
    sum1 += __shfl_xor_sync(0xffffffff, sum1, 2);
    float inv0 = 1.f / sum0;
    float inv1 = 1.f / sum1;

    // ---- O = P @ V  (S frags -> A frags; V^T in smem as B)
    float out[3][4];
    #pragma unroll
    for (int nv = 0; nv < 3; nv++)
        #pragma unroll
        for (int r = 0; r < 4; r++) out[nv][r] = 0.f;

    #pragma unroll
    for (int ksP = 0; ksP < 4; ksP++) {
        uint32_t a[4];
        a[0] = packbf(acc[2 * ksP    ][0], acc[2 * ksP    ][1]);
        a[1] = packbf(acc[2 * ksP    ][2], acc[2 * ksP    ][3]);
        a[2] = packbf(acc[2 * ksP + 1][0], acc[2 * ksP + 1][1]);
        a[3] = packbf(acc[2 * ksP + 1][2], acc[2 * ksP + 1][3]);
        #pragma unroll
        for (int nv = 0; nv < 3; nv++) {
            uint32_t b[2];
            b[0] = VtU[(h * 24 + nv * 8 + g) * 36 + ksP * 8 + t4    ];
            b[1] = VtU[(h * 24 + nv * 8 + g) * 36 + ksP * 8 + t4 + 4];
            mma_bf16(out[nv], a, b);
        }
    }

    // ---- write O (normalize by row sums)
    uint32_t* attU = (uint32_t*)g_att;
    size_t tok0 = (size_t)bn * NWT + r0;
    size_t tok1 = (size_t)bn * NWT + r1;
    #pragma unroll
    for (int nv = 0; nv < 3; nv++) {
        int col = h * 24 + nv * 8 + t4 * 2;
        attU[(tok0 * 96 + col) >> 1] = packbf(out[nv][0] * inv0, out[nv][1] * inv0);
        attU[(tok1 * 96 + col) >> 1] = packbf(out[nv][2] * inv1, out[nv][3] * inv1);
    }
}

// ============================================================
// K3: proj GEMM + window reverse + roll + residual + LN2
// ============================================================
__global__ void __launch_bounds__(256)
k_proj(const float* __restrict__ x, const float* __restrict__ pbias,
       const float* __restrict__ g2, const float* __restrict__ b2)
{
    extern __shared__ char smem[];
    uint32_t* As = (uint32_t*)smem;
    uint32_t* Bs = (uint32_t*)(smem + 26624);
    float* xs    = (float*)smem;
    int*   sprow = (int*)(smem + 49664);
    float* smu   = (float*)(smem + 50176);
    float* srs   = (float*)(smem + 50688);
    float* sg2   = (float*)(smem + 51200);
    float* sb2   = (float*)(smem + 51584);

    int tid = threadIdx.x;
    if (tid < 96) { sg2[tid] = g2[tid]; sb2[tid] = b2[tid]; }

    size_t bm = (size_t)blockIdx.x * 128;
    stage_A96(g_att, bm, As, tid);
    stage_B96(g_wproj, 0, Bs, tid);
    __syncthreads();

    int warp = tid >> 5, lane = tid & 31, g = lane >> 2, t4 = lane & 3;
    int wm = warp >> 1, wn = warp & 1;

    float acc[2][6][4];
    #pragma unroll
    for (int i = 0; i < 2; i++)
        #pragma unroll
        for (int j = 0; j < 6; j++)
            #pragma unroll
            for (int r = 0; r < 4; r++) acc[i][j][r] = 0.f;
    mma_tile96(As, Bs, acc, g, t4, wm, wn);
    __syncthreads();

    #pragma unroll
    for (int mt = 0; mt < 2; mt++)
        #pragma unroll
        for (int nt = 0; nt < 6; nt++) {
            int cl = wn * 48 + nt * 8 + t4 * 2;
            #pragma unroll
            for (int half = 0; half < 2; half++) {
                int rl = wm * 32 + mt * 16 + g + half * 8;
                xs[rl * 97 + cl    ] = acc[mt][nt][half * 2 + 0] + pbias[cl];
                xs[rl * 97 + cl + 1] = acc[mt][nt][half * 2 + 1] + pbias[cl + 1];
            }
        }
    __syncthreads();

    int t = tid & 127;
    int b, d, h, w;
    decode_tok((int)bm + t, b, d, h, w);
    int spoff = d * 4096 + h * 64 + w;
    size_t xbase = ((size_t)b * 96) * SP + spoff;
    if (tid < 128) sprow[tid] = b * SP + spoff;
    int c0 = tid >> 7;
    for (int c = c0; c < 96; c += 2)
        xs[t * 97 + c] += x[xbase + (size_t)c * SP];
    __syncthreads();

    if (tid < 128) {
        const float* row = xs + tid * 97;
        float s = 0.f, ss = 0.f;
        #pragma unroll
        for (int c = 0; c < 96; c++) { float v = row[c]; s += v; ss += v * v; }
        float mean = s * (1.f / 96.f);
        smu[tid] = mean;
        srs[tid] = rsqrtf(ss * (1.f / 96.f) - mean * mean + 1e-5f);
    }
    __syncthreads();

    #pragma unroll
    for (int tk = 0; tk < 16; tk++) {
        int tt = warp * 16 + tk;
        size_t row = (size_t)sprow[tt] * 96;
        float mu = smu[tt], rs = srs[tt];
        #pragma unroll
        for (int rep = 0; rep < 3; rep++) {
            int c = lane + rep * 32;
            float v = xs[tt * 97 + c];
            g_x2[row + c] = v;
            g_hn[row + c] = __float2bfloat16_rn((v - mu) * rs * sg2[c] + sb2[c]);
        }
    }
}

// ============================================================
// K4: fc1 GEMM + GELU
// ============================================================
__global__ void __launch_bounds__(256)
k_fc1(const float* __restrict__ f1bias)
{
    extern __shared__ char smem[];
    uint32_t* As = (uint32_t*)smem;
    uint32_t* Bs = (uint32_t*)(smem + 26624);

    int tid = threadIdx.x;
    size_t bm = (size_t)blockIdx.x * 128;
    stage_A96(g_hn, bm, As, tid);

    int warp = tid >> 5, lane = tid & 31, g = lane >> 2, t4 = lane & 3;
    int wm = warp >> 1, wn = warp & 1;

    for (int bt = 0; bt < 4; bt++) {
        if (bt) __syncthreads();
        stage_B96(g_wfc1, bt * 96, Bs, tid);
        __syncthreads();
        float acc[2][6][4];
        #pragma unroll
        for (int i = 0; i < 2; i++)
            #pragma unroll
            for (int j = 0; j < 6; j++)
                #pragma unroll
                for (int r = 0; r < 4; r++) acc[i][j][r] = 0.f;
        mma_tile96(As, Bs, acc, g, t4, wm, wn);
        #pragma unroll
        for (int mt = 0; mt < 2; mt++)
            #pragma unroll
            for (int nt = 0; nt < 6; nt++) {
                int ncol = wn * 48 + nt * 8 + t4 * 2;
                #pragma unroll
                for (int half = 0; half < 2; half++) {
                    size_t row = bm + wm * 32 + mt * 16 + g + half * 8;
                    float v0 = acc[mt][nt][half * 2 + 0] + f1bias[bt * 96 + ncol];
                    float v1 = acc[mt][nt][half * 2 + 1] + f1bias[bt * 96 + ncol + 1];
                    v0 = 0.5f * v0 * (1.f + erff(v0 * 0.70710678118654752f));
                    v1 = 0.5f * v1 * (1.f + erff(v1 * 0.70710678118654752f));
                    *(uint32_t*)&g_m1[row * 384 + bt * 96 + ncol] = packbf(v0, v1);
                }
            }
    }
}

// ============================================================
// K5: fc2 GEMM (K=384) + residual + transpose to out
// ============================================================
__global__ void __launch_bounds__(256)
k_fc2(const float* __restrict__ f2bias, float* __restrict__ out)
{
    extern __shared__ char smem[];
    uint32_t* As = (uint32_t*)smem;
    uint32_t* Bs = (uint32_t*)(smem + 26624);
    float* sout  = (float*)smem;

    int tid = threadIdx.x;
    size_t bm = (size_t)blockIdx.x * 128;
    int warp = tid >> 5, lane = tid & 31, g = lane >> 2, t4 = lane & 3;
    int wm = warp >> 1, wn = warp & 1;

    float acc[2][6][4];
    #pragma unroll
    for (int i = 0; i < 2; i++)
        #pragma unroll
        for (int j = 0; j < 6; j++)
            #pragma unroll
            for (int r = 0; r < 4; r++) acc[i][j][r] = 0.f;

    for (int kc = 0; kc < 4; kc++) {
        if (kc) __syncthreads();
        int k0 = kc * 96;
        for (int i = tid; i < 128 * 12; i += 256) {
            int row = i / 12, q = i - row * 12;
            ((uint4*)&As[row * PITCH])[q] = ((const uint4*)(g_m1 + (bm + row) * 384 + k0))[q];
        }
        for (int i = tid; i < 96 * 12; i += 256) {
            int row = i / 12, q = i - row * 12;
            ((uint4*)&Bs[row * PITCH])[q] = ((const uint4*)(g_wfc2 + (size_t)row * 384 + k0))[q];
        }
        __syncthreads();
        mma_tile96(As, Bs, acc, g, t4, wm, wn);
    }
    __syncthreads();

    int b   = (int)(bm >> 17);
    int sp0 = (int)(bm & (SP - 1));

    #pragma unroll
    for (int p = 0; p < 2; p++) {
        if (wn == p) {
            #pragma unroll
            for (int mt = 0; mt < 2; mt++)
                #pragma unroll
                for (int nt = 0; nt < 6; nt++) {
                    int cl = nt * 8 + t4 * 2;
                    #pragma unroll
                    for (int half = 0; half < 2; half++) {
                        int rl = wm * 32 + mt * 16 + g + half * 8;
                        float2 xv = *(const float2*)&g_x2[(bm + rl) * 96 + p * 48 + cl];
                        sout[(cl    ) * 132 + rl] = acc[mt][nt][half * 2 + 0] + f2bias[p * 48 + cl    ] + xv.x;
                        sout[(cl + 1) * 132 + rl] = acc[mt][nt][half * 2 + 1] + f2bias[p * 48 + cl + 1] + xv.y;
                    }
                }
        }
        __syncthreads();
        for (int i = tid; i < 48 * 128; i += 256) {
            int c = i >> 7, tk = i & 127;
            out[((size_t)b * 96 + p * 48 + c) * SP + sp0 + tk] = sout[c * 132 + tk];
        }
        __syncthreads();
    }
}

// ============================================================
// launch
// ============================================================
extern "C" void kernel_launch(void* const* d_in, const int* in_sizes, int n_in,
                              void* d_out, int out_size)
{
    const float* x    = (const float*)d_in[0];
    const float* n1g  = (const float*)d_in[1];
    const float* n1b  = (const float*)d_in[2];
    const float* qkvw = (const float*)d_in[3];
    const float* qkvb = (const float*)d_in[4];
    const float* rpb  = (const float*)d_in[5];
    const float* pw   = (const float*)d_in[6];
    const float* pb   = (const float*)d_in[7];
    const float* n2g  = (const float*)d_in[8];
    const float* n2b  = (const float*)d_in[9];
    const float* f1w  = (const float*)d_in[10];
    const float* f1b  = (const float*)d_in[11];
    const float* f2w  = (const float*)d_in[12];
    const float* f2b  = (const float*)d_in[13];
    float* out = (float*)d_out;

    static int smem_set = 0;
    if (!smem_set) {
        cudaFuncSetAttribute(k_qkv,  cudaFuncAttributeMaxDynamicSharedMemorySize, 48 * 1024);
        cudaFuncSetAttribute(k_attn, cudaFuncAttributeMaxDynamicSharedMemorySize, AT_SIZE);
        cudaFuncSetAttribute(k_proj, cudaFuncAttributeMaxDynamicSharedMemorySize, 52 * 1024);
        cudaFuncSetAttribute(k_fc1,  cudaFuncAttributeMaxDynamicSharedMemorySize, 47 * 1024);
        cudaFuncSetAttribute(k_fc2,  cudaFuncAttributeMaxDynamicSharedMemorySize, 47 * 1024);
        smem_set = 1;
    }

    const int SZ_QKV  = 46592 + 768;
    const int SZ_PROJ = 51968;
    const int SZ_GEMM = 46592;

    k_wconv<<<432, 256>>>(qkvw, pw, f1w, f2w);
    k_bias <<<32, 256>>>(rpb);
    k_qkv <<<NTOK / 128, 256, SZ_QKV >>>(x, n1g, n1b, qkvb);
    k_attn<<<BATCH * NWIN, 512, AT_SIZE>>>();
    k_proj<<<NTOK / 128, 256, SZ_PROJ>>>(x, pb, n2g, n2b);
    k_fc1 <<<NTOK / 128, 256, SZ_GEMM>>>(f1b);
    k_fc2 <<<NTOK / 128, 256, SZ_GEMM>>>(f2b, out);
}

// round 11
// speedup vs baseline: 1.1730x; 1.1730x over previous
#include <cuda_runtime.h>
#include <cuda_bf16.h>
#include <math.h>
#include <stdint.h>

// ---------------- problem constants ----------------
#define CDIM   96
#define DD     32
#define HH     64
#define WWD    64
#define BATCH  2
#define SP     131072
#define NTOK   (BATCH * SP)
#define NWIN   2048
#define NHEAD  4
#define HDIM   24
#define NWT    64

// ---------------- device scratch ----------------
__device__ __nv_bfloat16 g_qkv [(size_t)NTOK * 3 * CDIM];  // window-token-major (q pre-scaled)
__device__ __nv_bfloat16 g_att [(size_t)NTOK * CDIM];      // window-token-major
__device__ float         g_x2  [(size_t)NTOK * CDIM];      // residual, SPATIAL token-major
__device__ __nv_bfloat16 g_hn  [(size_t)NTOK * CDIM];      // LN2 out, SPATIAL token-major
__device__ uint32_t      g_biasF[8192];                    // fragment-ordered bias table
// bf16 weights
__device__ __nv_bfloat16 g_wqkv[288 * 96];
__device__ __nv_bfloat16 g_wproj[96 * 96];
__device__ __nv_bfloat16 g_wfc1[384 * 96];
__device__ __nv_bfloat16 g_wfc2[96 * 384];

__device__ __forceinline__ uint32_t packbf(float a, float b) {
    __nv_bfloat162 h = __floats2bfloat162_rn(a, b);
    return *reinterpret_cast<uint32_t*>(&h);
}
__device__ __forceinline__ float2 unpackbf(uint32_t u) {
    return __bfloat1622float2(*reinterpret_cast<const __nv_bfloat162*>(&u));
}

__global__ void k_wconv(const float* __restrict__ a, const float* __restrict__ b,
                        const float* __restrict__ c, const float* __restrict__ d)
{
    int i = blockIdx.x * 256 + threadIdx.x;
    if (i < 27648)            g_wqkv[i]          = __float2bfloat16_rn(a[i]);
    else if (i < 36864)       g_wproj[i - 27648] = __float2bfloat16_rn(b[i - 27648]);
    else if (i < 73728)       g_wfc1[i - 36864]  = __float2bfloat16_rn(c[i - 36864]);
    else if (i < 110592)      g_wfc2[i - 73728]  = __float2bfloat16_rn(d[i - 73728]);
}

// Precompute rel-pos bias table in mma-fragment order.
__global__ void k_bias(const float* __restrict__ rpb)
{
    int idx = blockIdx.x * 256 + threadIdx.x;   // 8192
    int t4 = idx & 3;
    int nt = (idx >> 2) & 7;
    int r  = (idx >> 5) & 63;
    int h  = idx >> 11;
    int j0 = nt * 8 + t4 * 2;
    int id = r >> 4, ih = (r >> 2) & 3, iw = r & 3;
    auto relf = [&](int j) {
        int jd = j >> 4, jh = (j >> 2) & 3, jw = j & 3;
        return (id - jd + 3) * 49 + (ih - jh + 3) * 7 + (iw - jw + 3);
    };
    float b0 = rpb[relf(j0) * NHEAD + h];
    float b1 = rpb[relf(j0 + 1) * NHEAD + h];
    uint32_t addr = (uint32_t)(((h * 8 + (r >> 4) * 2 + ((r >> 3) & 1)) * 8 + nt) * 32
                               + (r & 7) * 4 + t4);
    g_biasF[addr] = packbf(b0, b1);
}

// ---------------- mma helpers ----------------
#define PITCH 52

__device__ __forceinline__ void mma_bf16(float c[4], const uint32_t a[4], const uint32_t b[2]) {
    asm volatile(
        "mma.sync.aligned.m16n8k16.row.col.f32.bf16.bf16.f32 "
        "{%0,%1,%2,%3}, {%4,%5,%6,%7}, {%8,%9}, {%0,%1,%2,%3};\n"
        : "+f"(c[0]), "+f"(c[1]), "+f"(c[2]), "+f"(c[3])
        : "r"(a[0]), "r"(a[1]), "r"(a[2]), "r"(a[3]), "r"(b[0]), "r"(b[1]));
}

// 8-warp (256-thread) layout: wm 0..3 (32-row slab), wn 0..1 (48-col half)
__device__ __forceinline__ void mma_tile96(const uint32_t* As, const uint32_t* Bs,
                                           float acc[2][6][4], int g, int t4, int wm, int wn)
{
    #pragma unroll
    for (int ks = 0; ks < 6; ks++) {
        int k8 = ks * 8;
        uint32_t af[2][4];
        #pragma unroll
        for (int mt = 0; mt < 2; mt++) {
            int rb = wm * 32 + mt * 16;
            af[mt][0] = As[(rb + g    ) * PITCH + k8 + t4    ];
            af[mt][1] = As[(rb + g + 8) * PITCH + k8 + t4    ];
            af[mt][2] = As[(rb + g    ) * PITCH + k8 + t4 + 4];
            af[mt][3] = As[(rb + g + 8) * PITCH + k8 + t4 + 4];
        }
        uint32_t bf[6][2];
        #pragma unroll
        for (int nt = 0; nt < 6; nt++) {
            int nb = wn * 48 + nt * 8;
            bf[nt][0] = Bs[(nb + g) * PITCH + k8 + t4    ];
            bf[nt][1] = Bs[(nb + g) * PITCH + k8 + t4 + 4];
        }
        #pragma unroll
        for (int mt = 0; mt < 2; mt++)
            #pragma unroll
            for (int nt = 0; nt < 6; nt++)
                mma_bf16(acc[mt][nt], af[mt], bf[nt]);
    }
}

// 16-warp (512-thread) layout: wm 0..3 (32-row slab), wn 0..3 (24-col slab)
__device__ __forceinline__ void mma_tile96_w16(const uint32_t* As, const uint32_t* Bs,
                                               float acc[2][3][4], int g, int t4, int wm, int wn)
{
    #pragma unroll
    for (int ks = 0; ks < 6; ks++) {
        int k8 = ks * 8;
        uint32_t af[2][4];
        #pragma unroll
        for (int mt = 0; mt < 2; mt++) {
            int rb = wm * 32 + mt * 16;
            af[mt][0] = As[(rb + g    ) * PITCH + k8 + t4    ];
            af[mt][1] = As[(rb + g + 8) * PITCH + k8 + t4    ];
            af[mt][2] = As[(rb + g    ) * PITCH + k8 + t4 + 4];
            af[mt][3] = As[(rb + g + 8) * PITCH + k8 + t4 + 4];
        }
        uint32_t bf[3][2];
        #pragma unroll
        for (int nt = 0; nt < 3; nt++) {
            int nb = wn * 24 + nt * 8;
            bf[nt][0] = Bs[(nb + g) * PITCH + k8 + t4    ];
            bf[nt][1] = Bs[(nb + g) * PITCH + k8 + t4 + 4];
        }
        #pragma unroll
        for (int mt = 0; mt < 2; mt++)
            #pragma unroll
            for (int nt = 0; nt < 3; nt++)
                mma_bf16(acc[mt][nt], af[mt], bf[nt]);
    }
}

__device__ __forceinline__ void stage_A96(const __nv_bfloat16* A, size_t bm, uint32_t* As, int tid) {
    for (int i = tid; i < 128 * 12; i += 256) {
        int row = i / 12, q = i - row * 12;
        ((uint4*)&As[row * PITCH])[q] = ((const uint4*)(A + (bm + row) * 96))[q];
    }
}
__device__ __forceinline__ void stage_B96(const __nv_bfloat16* Wb, int bn, uint32_t* Bs, int tid) {
    for (int i = tid; i < 96 * 12; i += 256) {
        int row = i / 12, q = i - row * 12;
        ((uint4*)&Bs[row * PITCH])[q] = ((const uint4*)(Wb + (size_t)(bn + row) * 96))[q];
    }
}

__device__ __forceinline__ void decode_tok(int r, int& b, int& d, int& h, int& w) {
    int widx = r >> 6, inner = r & 63;
    b = widx >> 11;
    int wi = widx & 2047;
    int wd = wi >> 8, wh = (wi >> 4) & 15, ww = wi & 15;
    int id = inner >> 4, ih = (inner >> 2) & 3, iw = inner & 3;
    d = (wd * 4 + id + 2) & 31;
    h = (wh * 4 + ih + 2) & 63;
    w = (ww * 4 + iw + 2) & 63;
}

// ============================================================
// K1: fused LN1 + roll + window + qkv GEMM. q output pre-scaled by 24^-0.5.
// ============================================================
__global__ void __launch_bounds__(256)
k_qkv(const float* __restrict__ x, const float* __restrict__ gw,
      const float* __restrict__ gb, const float* __restrict__ qbias)
{
    extern __shared__ char smem[];
    uint32_t* As = (uint32_t*)smem;
    uint32_t* Bs = (uint32_t*)(smem + 26624);
    float* sgw = (float*)(smem + 46592);
    float* sgb = sgw + 96;

    int tid = threadIdx.x;
    if (tid < 96) { sgw[tid] = gw[tid]; sgb[tid] = gb[tid]; }

    size_t bm = (size_t)blockIdx.x * 128;
    int t = tid & 127;
    int b, d, h, w;
    decode_tok((int)bm + t, b, d, h, w);
    size_t xbase = ((size_t)b * 96) * SP + (size_t)d * 4096 + h * 64 + w;
    int c0 = tid >> 7;

    for (int p = c0; p < 48; p += 2) {
        float v0 = x[xbase + (size_t)(2 * p) * SP];
        float v1 = x[xbase + (size_t)(2 * p + 1) * SP];
        As[t * PITCH + p] = packbf(v0, v1);
    }
    __syncthreads();

    if (tid < 128) {
        uint32_t* row = As + tid * PITCH;
        float s = 0.f, ss = 0.f;
        #pragma unroll
        for (int p = 0; p < 48; p++) {
            float2 f = unpackbf(row[p]);
            s += f.x + f.y; ss += f.x * f.x + f.y * f.y;
        }
        float mean = s * (1.f / 96.f);
        float rstd = rsqrtf(ss * (1.f / 96.f) - mean * mean + 1e-5f);
        #pragma unroll
        for (int p = 0; p < 48; p++) {
            float2 f = unpackbf(row[p]);
            f.x = (f.x - mean) * rstd * sgw[2 * p] + sgb[2 * p];
            f.y = (f.y - mean) * rstd * sgw[2 * p + 1] + sgb[2 * p + 1];
            row[p] = packbf(f.x, f.y);
        }
    }
    __syncthreads();

    int warp = tid >> 5, lane = tid & 31, g = lane >> 2, t4 = lane & 3;
    int wm = warp >> 1, wn = warp & 1;

    for (int bt = 0; bt < 3; bt++) {
        stage_B96(g_wqkv, bt * 96, Bs, tid);
        __syncthreads();
        float acc[2][6][4];
        #pragma unroll
        for (int i = 0; i < 2; i++)
            #pragma unroll
            for (int j = 0; j < 6; j++)
                #pragma unroll
                for (int r = 0; r < 4; r++) acc[i][j][r] = 0.f;
        mma_tile96(As, Bs, acc, g, t4, wm, wn);
        float scale = (bt == 0) ? 0.2041241452319315f : 1.0f;
        #pragma unroll
        for (int mt = 0; mt < 2; mt++)
            #pragma unroll
            for (int nt = 0; nt < 6; nt++) {
                int ncol = wn * 48 + nt * 8 + t4 * 2;
                #pragma unroll
                for (int half = 0; half < 2; half++) {
                    size_t row = bm + wm * 32 + mt * 16 + g + half * 8;
                    float v0 = (acc[mt][nt][half * 2 + 0] + qbias[bt * 96 + ncol]) * scale;
                    float v1 = (acc[mt][nt][half * 2 + 1] + qbias[bt * 96 + ncol + 1]) * scale;
                    *(uint32_t*)&g_qkv[row * 288 + bt * 96 + ncol] = packbf(v0, v1);
                }
            }
        __syncthreads();
    }
}

// ============================================================
// K2: tensor-core windowed attention (bit-op staging, no divisions).
// ============================================================
#define AT_QS   0
#define AT_KS   5120
#define AT_VT   10240        // bf16 view, 4*24 rows * 36 u32 pitch
#define AT_BF   13696
#define AT_GT   21888
#define AT_SIZE (21952 * 4)  // 87808 B

__global__ void __launch_bounds__(512)
k_attn()
{
    extern __shared__ uint32_t sm[];
    uint32_t* Qs = sm + AT_QS;
    uint32_t* Ks = sm + AT_KS;
    uint32_t* VtU = sm + AT_VT;
    __nv_bfloat16* Vt = (__nv_bfloat16*)(sm + AT_VT);
    uint32_t* bF = sm + AT_BF;
    int* gtk = (int*)(sm + AT_GT);

    int tid = threadIdx.x;
    int bn  = blockIdx.x;
    int wi  = bn & (NWIN - 1);
    int wd = wi >> 8, wh = (wi >> 4) & 15, ww = wi & 15;
    bool interior = (wd != 7) && (wh != 15) && (ww != 15);

    const uint4* src4 = (const uint4*)(g_qkv + (size_t)bn * NWT * 288);
    const uint32_t* srcU = (const uint32_t*)src4;

    // Q/K staging + zero-pad: thread -> (sec = tid>>8, h = (tid>>6)&3, r = tid&63), q = 0..2
    {
        int sec = tid >> 8;
        int hq  = (tid >> 6) & 3;
        int r   = tid & 63;
        const uint4* s4 = src4 + r * 36 + sec * 12 + hq * 3;
        uint32_t* dst = (sec ? Ks : Qs) + (hq * 64 + r) * 20;
        #pragma unroll
        for (int q = 0; q < 3; q++)
            *(uint4*)(dst + q * 4) = s4[q];
        *(uint4*)(dst + 12) = make_uint4(0, 0, 0, 0);
    }
    // V transpose: thread -> (h = tid>>7, j = (tid&127)>>1, p = (tid&1)*6 + m)
    {
        int hv = tid >> 7;
        int w2 = tid & 127;
        int j  = w2 >> 1;
        int pb = (w2 & 1) * 6;
        const uint32_t* s = srcU + j * 144 + 96 + hv * 12 + pb;
        #pragma unroll
        for (int m = 0; m < 6; m++) {
            uint32_t v = s[m];
            __nv_bfloat162 bv = *reinterpret_cast<__nv_bfloat162*>(&v);
            int p = pb + m;
            Vt[(hv * 24 + 2 * p    ) * 72 + j] = bv.x;
            Vt[(hv * 24 + 2 * p + 1) * 72 + j] = bv.y;
        }
    }
    // bias table
    {
        const uint4* gb4 = (const uint4*)g_biasF;
        uint4* sb4 = (uint4*)bF;
        #pragma unroll
        for (int m = 0; m < 4; m++) sb4[tid + m * 512] = gb4[tid + m * 512];
    }
    // group ids
    if (tid < 64) {
        int id = tid >> 4, ih = (tid >> 2) & 3, iw = tid & 3;
        int da = wd * 4 + id, ha = wh * 4 + ih, wa = ww * 4 + iw;
        int rd = (da < DD  - 4) ? 0 : ((da < DD  - 2) ? 1 : 2);
        int rh = (ha < HH  - 4) ? 0 : ((ha < HH  - 2) ? 1 : 2);
        int rw = (wa < WWD - 4) ? 0 : ((wa < WWD - 2) ? 1 : 2);
        gtk[tid] = rd * 9 + rh * 3 + rw;
    }
    __syncthreads();

    int w = tid >> 5, lane = tid & 31;
    int g = lane >> 2, t4 = lane & 3;
    int h  = w >> 2;          // head
    int rq = w & 3;           // 16-row slab
    const uint32_t* Qh = Qs + h * 1280;
    const uint32_t* Kh = Ks + h * 1280;

    // ---- S = Q @ K^T  (m16 x n64, k=32 padded)
    float acc[8][4];
    #pragma unroll
    for (int nt = 0; nt < 8; nt++)
        #pragma unroll
        for (int r = 0; r < 4; r++) acc[nt][r] = 0.f;

    #pragma unroll
    for (int ks = 0; ks < 2; ks++) {
        uint32_t a[4];
        a[0] = Qh[(rq * 16 + g    ) * 20 + ks * 8 + t4    ];
        a[1] = Qh[(rq * 16 + g + 8) * 20 + ks * 8 + t4    ];
        a[2] = Qh[(rq * 16 + g    ) * 20 + ks * 8 + t4 + 4];
        a[3] = Qh[(rq * 16 + g + 8) * 20 + ks * 8 + t4 + 4];
        #pragma unroll
        for (int nt = 0; nt < 8; nt++) {
            uint32_t b[2];
            b[0] = Kh[(nt * 8 + g) * 20 + ks * 8 + t4    ];
            b[1] = Kh[(nt * 8 + g) * 20 + ks * 8 + t4 + 4];
            mma_bf16(acc[nt], a, b);
        }
    }

    // ---- softmax in fragments (unnormalized)
    int r0 = rq * 16 + g;
    int r1 = r0 + 8;
    float sum0 = 0.f, sum1 = 0.f;
    int base0 = ((h * 8 + rq * 2 + 0) * 8) * 32 + lane;
    int base1 = ((h * 8 + rq * 2 + 1) * 8) * 32 + lane;

    if (interior) {
        #pragma unroll
        for (int nt = 0; nt < 8; nt++) {
            float2 f0 = unpackbf(bF[base0 + nt * 32]);
            float2 f1 = unpackbf(bF[base1 + nt * 32]);
            float e0 = __expf(acc[nt][0] + f0.x);
            float e1 = __expf(acc[nt][1] + f0.y);
            float e2 = __expf(acc[nt][2] + f1.x);
            float e3 = __expf(acc[nt][3] + f1.y);
            acc[nt][0] = e0; acc[nt][1] = e1; acc[nt][2] = e2; acc[nt][3] = e3;
            sum0 += e0 + e1; sum1 += e2 + e3;
        }
    } else {
        int rg0 = gtk[r0], rg1 = gtk[r1];
        #pragma unroll
        for (int nt = 0; nt < 8; nt++) {
            int cA = nt * 8 + t4 * 2;
            int m0 = gtk[cA], m1 = gtk[cA + 1];
            float2 f0 = unpackbf(bF[base0 + nt * 32]);
            float2 f1 = unpackbf(bF[base1 + nt * 32]);
            float e0 = (m0 == rg0) ? __expf(acc[nt][0] + f0.x) : 0.f;
            float e1 = (m1 == rg0) ? __expf(acc[nt][1] + f0.y) : 0.f;
            float e2 = (m0 == rg1) ? __expf(acc[nt][2] + f1.x) : 0.f;
            float e3 = (m1 == rg1) ? __expf(acc[nt][3] + f1.y) : 0.f;
            acc[nt][0] = e0; acc[nt][1] = e1; acc[nt][2] = e2; acc[nt][3] = e3;
            sum0 += e0 + e1; sum1 += e2 + e3;
        }
    }
    sum0 += __shfl_xor_sync(0xffffffff, sum0, 1);
    sum0 += __shfl_xor_sync(0xffffffff, sum0, 2);
    sum1 += __shfl_xor_sync(0xffffffff, sum1, 1);
    sum1 += __shfl_xor_sync(0xffffffff, sum1, 2);
    float inv0 = 1.f / sum0;
    float inv1 = 1.f / sum1;

    // ---- O = P @ V
    float out[3][4];
    #pragma unroll
    for (int nv = 0; nv < 3; nv++)
        #pragma unroll
        for (int r = 0; r < 4; r++) out[nv][r] = 0.f;

    #pragma unroll
    for (int ksP = 0; ksP < 4; ksP++) {
        uint32_t a[4];
        a[0] = packbf(acc[2 * ksP    ][0], acc[2 * ksP    ][1]);
        a[1] = packbf(acc[2 * ksP    ][2], acc[2 * ksP    ][3]);
        a[2] = packbf(acc[2 * ksP + 1][0], acc[2 * ksP + 1][1]);
        a[3] = packbf(acc[2 * ksP + 1][2], acc[2 * ksP + 1][3]);
        #pragma unroll
        for (int nv = 0; nv < 3; nv++) {
            uint32_t b[2];
            b[0] = VtU[(h * 24 + nv * 8 + g) * 36 + ksP * 8 + t4    ];
            b[1] = VtU[(h * 24 + nv * 8 + g) * 36 + ksP * 8 + t4 + 4];
            mma_bf16(out[nv], a, b);
        }
    }

    // ---- write O
    uint32_t* attU = (uint32_t*)g_att;
    size_t tok0 = (size_t)bn * NWT + r0;
    size_t tok1 = (size_t)bn * NWT + r1;
    #pragma unroll
    for (int nv = 0; nv < 3; nv++) {
        int col = h * 24 + nv * 8 + t4 * 2;
        attU[(tok0 * 96 + col) >> 1] = packbf(out[nv][0] * inv0, out[nv][1] * inv0);
        attU[(tok1 * 96 + col) >> 1] = packbf(out[nv][2] * inv1, out[nv][3] * inv1);
    }
}

// ============================================================
// K3: proj GEMM + window reverse + roll + residual + LN2
// ============================================================
__global__ void __launch_bounds__(256)
k_proj(const float* __restrict__ x, const float* __restrict__ pbias,
       const float* __restrict__ g2, const float* __restrict__ b2)
{
    extern __shared__ char smem[];
    uint32_t* As = (uint32_t*)smem;
    uint32_t* Bs = (uint32_t*)(smem + 26624);
    float* xs    = (float*)smem;
    int*   sprow = (int*)(smem + 49664);
    float* smu   = (float*)(smem + 50176);
    float* srs   = (float*)(smem + 50688);
    float* sg2   = (float*)(smem + 51200);
    float* sb2   = (float*)(smem + 51584);

    int tid = threadIdx.x;
    if (tid < 96) { sg2[tid] = g2[tid]; sb2[tid] = b2[tid]; }

    size_t bm = (size_t)blockIdx.x * 128;
    stage_A96(g_att, bm, As, tid);
    stage_B96(g_wproj, 0, Bs, tid);
    __syncthreads();

    int warp = tid >> 5, lane = tid & 31, g = lane >> 2, t4 = lane & 3;
    int wm = warp >> 1, wn = warp & 1;

    float acc[2][6][4];
    #pragma unroll
    for (int i = 0; i < 2; i++)
        #pragma unroll
        for (int j = 0; j < 6; j++)
            #pragma unroll
            for (int r = 0; r < 4; r++) acc[i][j][r] = 0.f;
    mma_tile96(As, Bs, acc, g, t4, wm, wn);
    __syncthreads();

    #pragma unroll
    for (int mt = 0; mt < 2; mt++)
        #pragma unroll
        for (int nt = 0; nt < 6; nt++) {
            int cl = wn * 48 + nt * 8 + t4 * 2;
            #pragma unroll
            for (int half = 0; half < 2; half++) {
                int rl = wm * 32 + mt * 16 + g + half * 8;
                xs[rl * 97 + cl    ] = acc[mt][nt][half * 2 + 0] + pbias[cl];
                xs[rl * 97 + cl + 1] = acc[mt][nt][half * 2 + 1] + pbias[cl + 1];
            }
        }
    __syncthreads();

    int t = tid & 127;
    int b, d, h, w;
    decode_tok((int)bm + t, b, d, h, w);
    int spoff = d * 4096 + h * 64 + w;
    size_t xbase = ((size_t)b * 96) * SP + spoff;
    if (tid < 128) sprow[tid] = b * SP + spoff;
    int c0 = tid >> 7;
    for (int c = c0; c < 96; c += 2)
        xs[t * 97 + c] += x[xbase + (size_t)c * SP];
    __syncthreads();

    if (tid < 128) {
        const float* row = xs + tid * 97;
        float s = 0.f, ss = 0.f;
        #pragma unroll
        for (int c = 0; c < 96; c++) { float v = row[c]; s += v; ss += v * v; }
        float mean = s * (1.f / 96.f);
        smu[tid] = mean;
        srs[tid] = rsqrtf(ss * (1.f / 96.f) - mean * mean + 1e-5f);
    }
    __syncthreads();

    #pragma unroll
    for (int tk = 0; tk < 16; tk++) {
        int tt = warp * 16 + tk;
        size_t row = (size_t)sprow[tt] * 96;
        float mu = smu[tt], rs = srs[tt];
        #pragma unroll
        for (int rep = 0; rep < 3; rep++) {
            int c = lane + rep * 32;
            float v = xs[tt * 97 + c];
            g_x2[row + c] = v;
            g_hn[row + c] = __float2bfloat16_rn((v - mu) * rs * sg2[c] + sb2[c]);
        }
    }
}

// ============================================================
// K4: fused MLP, M=128, 512 threads. fc1+GELU -> smem m1 (4 chunks),
// fc2 accumulates from smem, epilogue adds x2 + transposes to out.
// ============================================================
#define MLP_BS   26624
#define MLP_M1   46592
#define MLP_SIZE (46592 + 4 * 26624)   // 153088 B

__global__ void __launch_bounds__(512)
k_mlp(const float* __restrict__ f1bias, const float* __restrict__ f2bias,
      float* __restrict__ out)
{
    extern __shared__ char smem[];
    uint32_t* As   = (uint32_t*)smem;
    uint32_t* Bs   = (uint32_t*)(smem + MLP_BS);
    float*    sout = (float*)smem;    // reuse As region after fc1 reads finish

    int tid = threadIdx.x;
    size_t bm = (size_t)blockIdx.x * 128;
    int warp = tid >> 5, lane = tid & 31, g = lane >> 2, t4 = lane & 3;
    int wm = warp >> 2;     // 0..3: 32-row slab
    int wn = warp & 3;      // 0..3: 24-col slab

    // stage A (g_hn): thread -> row = tid>>2, q = (tid&3)*3 + m
    {
        int rowA = tid >> 2;
        int qb = (tid & 3) * 3;
        const uint4* sA = (const uint4*)(g_hn + (bm + rowA) * 96) + qb;
        uint4* dA = (uint4*)&As[rowA * PITCH] + qb;
        dA[0] = sA[0]; dA[1] = sA[1]; dA[2] = sA[2];
    }

    // ---- fc1 + GELU -> m1 chunks in smem
    for (int bt = 0; bt < 4; bt++) {
        if (bt) __syncthreads();
        if (tid < 384) {
            int row = tid >> 2;
            int qb = (tid & 3) * 3;
            const uint4* sB = (const uint4*)(g_wfc1 + (size_t)(bt * 96 + row) * 96) + qb;
            uint4* dB = (uint4*)&Bs[row * PITCH] + qb;
            dB[0] = sB[0]; dB[1] = sB[1]; dB[2] = sB[2];
        }
        __syncthreads();
        float acc[2][3][4];
        #pragma unroll
        for (int i = 0; i < 2; i++)
            #pragma unroll
            for (int j = 0; j < 3; j++)
                #pragma unroll
                for (int r = 0; r < 4; r++) acc[i][j][r] = 0.f;
        mma_tile96_w16(As, Bs, acc, g, t4, wm, wn);
        uint32_t* m1c = (uint32_t*)(smem + MLP_M1 + bt * 26624);
        #pragma unroll
        for (int mt = 0; mt < 2; mt++)
            #pragma unroll
            for (int nt = 0; nt < 3; nt++) {
                int ncol = wn * 24 + nt * 8 + t4 * 2;
                #pragma unroll
                for (int half = 0; half < 2; half++) {
                    int row = wm * 32 + mt * 16 + g + half * 8;
                    float v0 = acc[mt][nt][half * 2 + 0] + f1bias[bt * 96 + ncol];
                    float v1 = acc[mt][nt][half * 2 + 1] + f1bias[bt * 96 + ncol + 1];
                    v0 = 0.5f * v0 * (1.f + erff(v0 * 0.70710678118654752f));
                    v1 = 0.5f * v1 * (1.f + erff(v1 * 0.70710678118654752f));
                    m1c[row * PITCH + (ncol >> 1)] = packbf(v0, v1);
                }
            }
    }

    // ---- fc2: accumulate over 4 K-chunks from smem m1
    float acc2[2][3][4];
    #pragma unroll
    for (int i = 0; i < 2; i++)
        #pragma unroll
        for (int j = 0; j < 3; j++)
            #pragma unroll
            for (int r = 0; r < 4; r++) acc2[i][j][r] = 0.f;

    for (int kc = 0; kc < 4; kc++) {
        __syncthreads();   // first iter also guards m1 writes
        if (tid < 384) {
            int row = tid >> 2;
            int qb = (tid & 3) * 3;
            const uint4* sB = (const uint4*)(g_wfc2 + (size_t)row * 384 + kc * 96) + qb;
            uint4* dB = (uint4*)&Bs[row * PITCH] + qb;
            dB[0] = sB[0]; dB[1] = sB[1]; dB[2] = sB[2];
        }
        __syncthreads();
        const uint32_t* m1c = (const uint32_t*)(smem + MLP_M1 + kc * 26624);
        mma_tile96_w16(m1c, Bs, acc2, g, t4, wm, wn);
    }
    __syncthreads();

    // ---- epilogue: + bias + x2 residual, transpose to channel-major out
    int b   = (int)(bm >> 17);
    int sp0 = (int)(bm & (SP - 1));

    #pragma unroll
    for (int p = 0; p < 2; p++) {
        if ((wn >> 1) == p) {
            #pragma unroll
            for (int mt = 0; mt < 2; mt++)
                #pragma unroll
                for (int nt = 0; nt < 3; nt++) {
                    int cl = (wn & 1) * 24 + nt * 8 + t4 * 2;   // 0..47
                    #pragma unroll
                    for (int half = 0; half < 2; half++) {
                        int rl = wm * 32 + mt * 16 + g + half * 8;
                        float2 xv = *(const float2*)&g_x2[(bm + rl) * 96 + p * 48 + cl];
                        sout[(cl    ) * 132 + rl] = acc2[mt][nt][half * 2 + 0] + f2bias[p * 48 + cl    ] + xv.x;
                        sout[(cl + 1) * 132 + rl] = acc2[mt][nt][half * 2 + 1] + f2bias[p * 48 + cl + 1] + xv.y;
                    }
                }
        }
        __syncthreads();
        for (int i = tid; i < 48 * 128; i += 512) {
            int c = i >> 7, tk = i & 127;
            out[((size_t)b * 96 + p * 48 + c) * SP + sp0 + tk] = sout[c * 132 + tk];
        }
        __syncthreads();
    }
}

// ============================================================
// launch
// ============================================================
extern "C" void kernel_launch(void* const* d_in, const int* in_sizes, int n_in,
                              void* d_out, int out_size)
{
    const float* x    = (const float*)d_in[0];
    const float* n1g  = (const float*)d_in[1];
    const float* n1b  = (const float*)d_in[2];
    const float* qkvw = (const float*)d_in[3];
    const float* qkvb = (const float*)d_in[4];
    const float* rpb  = (const float*)d_in[5];
    const float* pw   = (const float*)d_in[6];
    const float* pb   = (const float*)d_in[7];
    const float* n2g  = (const float*)d_in[8];
    const float* n2b  = (const float*)d_in[9];
    const float* f1w  = (const float*)d_in[10];
    const float* f1b  = (const float*)d_in[11];
    const float* f2w  = (const float*)d_in[12];
    const float* f2b  = (const float*)d_in[13];
    float* out = (float*)d_out;

    static int smem_set = 0;
    if (!smem_set) {
        cudaFuncSetAttribute(k_qkv,  cudaFuncAttributeMaxDynamicSharedMemorySize, 48 * 1024);
        cudaFuncSetAttribute(k_attn, cudaFuncAttributeMaxDynamicSharedMemorySize, AT_SIZE);
        cudaFuncSetAttribute(k_proj, cudaFuncAttributeMaxDynamicSharedMemorySize, 52 * 1024);
        cudaFuncSetAttribute(k_mlp,  cudaFuncAttributeMaxDynamicSharedMemorySize, MLP_SIZE);
        smem_set = 1;
    }

    const int SZ_QKV  = 46592 + 768;
    const int SZ_PROJ = 51968;

    k_wconv<<<432, 256>>>(qkvw, pw, f1w, f2w);
    k_bias <<<32, 256>>>(rpb);
    k_qkv <<<NTOK / 128, 256, SZ_QKV >>>(x, n1g, n1b, qkvb);
    k_attn<<<BATCH * NWIN, 512, AT_SIZE>>>();
    k_proj<<<NTOK / 128, 256, SZ_PROJ>>>(x, pb, n2g, n2b);
    k_mlp <<<NTOK / 128, 512, MLP_SIZE>>>(f1b, f2b, out);
}

// round 12
// speedup vs baseline: 1.2094x; 1.0311x over previous
#include <cuda_runtime.h>
#include <cuda_bf16.h>
#include <math.h>
#include <stdint.h>

// ---------------- problem constants ----------------
#define CDIM   96
#define DD     32
#define HH     64
#define WWD    64
#define BATCH  2
#define SP     131072
#define NTOK   (BATCH * SP)
#define NWIN   2048
#define NHEAD  4
#define HDIM   24
#define NWT    64

// ---------------- device scratch ----------------
__device__ __nv_bfloat16 g_qkv [(size_t)NTOK * 3 * CDIM];  // window-token-major (q pre-scaled)
__device__ __nv_bfloat16 g_att [(size_t)NTOK * CDIM];      // window-token-major
__device__ float         g_x2  [(size_t)NTOK * CDIM];      // residual, SPATIAL token-major
__device__ __nv_bfloat16 g_hn  [(size_t)NTOK * CDIM];      // LN2 out, SPATIAL token-major
__device__ uint32_t      g_biasF[8192];                    // fragment-ordered bias table
// bf16 weights
__device__ __nv_bfloat16 g_wqkv[288 * 96];
__device__ __nv_bfloat16 g_wproj[96 * 96];
__device__ __nv_bfloat16 g_wfc1[384 * 96];
__device__ __nv_bfloat16 g_wfc2[96 * 384];

__device__ __forceinline__ uint32_t packbf(float a, float b) {
    __nv_bfloat162 h = __floats2bfloat162_rn(a, b);
    return *reinterpret_cast<uint32_t*>(&h);
}
__device__ __forceinline__ float2 unpackbf(uint32_t u) {
    return __bfloat1622float2(*reinterpret_cast<const __nv_bfloat162*>(&u));
}

__global__ void k_wconv(const float* __restrict__ a, const float* __restrict__ b,
                        const float* __restrict__ c, const float* __restrict__ d)
{
    int i = blockIdx.x * 256 + threadIdx.x;
    if (i < 27648)            g_wqkv[i]          = __float2bfloat16_rn(a[i]);
    else if (i < 36864)       g_wproj[i - 27648] = __float2bfloat16_rn(b[i - 27648]);
    else if (i < 73728)       g_wfc1[i - 36864]  = __float2bfloat16_rn(c[i - 36864]);
    else if (i < 110592)      g_wfc2[i - 73728]  = __float2bfloat16_rn(d[i - 73728]);
}

// Precompute rel-pos bias table in mma-fragment order.
__global__ void k_bias(const float* __restrict__ rpb)
{
    int idx = blockIdx.x * 256 + threadIdx.x;   // 8192
    int t4 = idx & 3;
    int nt = (idx >> 2) & 7;
    int r  = (idx >> 5) & 63;
    int h  = idx >> 11;
    int j0 = nt * 8 + t4 * 2;
    int id = r >> 4, ih = (r >> 2) & 3, iw = r & 3;
    auto relf = [&](int j) {
        int jd = j >> 4, jh = (j >> 2) & 3, jw = j & 3;
        return (id - jd + 3) * 49 + (ih - jh + 3) * 7 + (iw - jw + 3);
    };
    float b0 = rpb[relf(j0) * NHEAD + h];
    float b1 = rpb[relf(j0 + 1) * NHEAD + h];
    uint32_t addr = (uint32_t)(((h * 8 + (r >> 4) * 2 + ((r >> 3) & 1)) * 8 + nt) * 32
                               + (r & 7) * 4 + t4);
    g_biasF[addr] = packbf(b0, b1);
}

// ---------------- mma helpers ----------------
#define PITCH 52

__device__ __forceinline__ void mma_bf16(float c[4], const uint32_t a[4], const uint32_t b[2]) {
    asm volatile(
        "mma.sync.aligned.m16n8k16.row.col.f32.bf16.bf16.f32 "
        "{%0,%1,%2,%3}, {%4,%5,%6,%7}, {%8,%9}, {%0,%1,%2,%3};\n"
        : "+f"(c[0]), "+f"(c[1]), "+f"(c[2]), "+f"(c[3])
        : "r"(a[0]), "r"(a[1]), "r"(a[2]), "r"(a[3]), "r"(b[0]), "r"(b[1]));
}

// 8-warp (256-thread) layout: wm 0..3 (32-row slab), wn 0..1 (48-col half)
__device__ __forceinline__ void mma_tile96(const uint32_t* As, const uint32_t* Bs,
                                           float acc[2][6][4], int g, int t4, int wm, int wn)
{
    #pragma unroll
    for (int ks = 0; ks < 6; ks++) {
        int k8 = ks * 8;
        uint32_t af[2][4];
        #pragma unroll
        for (int mt = 0; mt < 2; mt++) {
            int rb = wm * 32 + mt * 16;
            af[mt][0] = As[(rb + g    ) * PITCH + k8 + t4    ];
            af[mt][1] = As[(rb + g + 8) * PITCH + k8 + t4    ];
            af[mt][2] = As[(rb + g    ) * PITCH + k8 + t4 + 4];
            af[mt][3] = As[(rb + g + 8) * PITCH + k8 + t4 + 4];
        }
        uint32_t bf[6][2];
        #pragma unroll
        for (int nt = 0; nt < 6; nt++) {
            int nb = wn * 48 + nt * 8;
            bf[nt][0] = Bs[(nb + g) * PITCH + k8 + t4    ];
            bf[nt][1] = Bs[(nb + g) * PITCH + k8 + t4 + 4];
        }
        #pragma unroll
        for (int mt = 0; mt < 2; mt++)
            #pragma unroll
            for (int nt = 0; nt < 6; nt++)
                mma_bf16(acc[mt][nt], af[mt], bf[nt]);
    }
}

// 16-warp (512-thread) layout: wm 0..3 (32-row slab), wn 0..3 (24-col slab)
__device__ __forceinline__ void mma_tile96_w16(const uint32_t* As, const uint32_t* Bs,
                                               float acc[2][3][4], int g, int t4, int wm, int wn)
{
    #pragma unroll
    for (int ks = 0; ks < 6; ks++) {
        int k8 = ks * 8;
        uint32_t af[2][4];
        #pragma unroll
        for (int mt = 0; mt < 2; mt++) {
            int rb = wm * 32 + mt * 16;
            af[mt][0] = As[(rb + g    ) * PITCH + k8 + t4    ];
            af[mt][1] = As[(rb + g + 8) * PITCH + k8 + t4    ];
            af[mt][2] = As[(rb + g    ) * PITCH + k8 + t4 + 4];
            af[mt][3] = As[(rb + g + 8) * PITCH + k8 + t4 + 4];
        }
        uint32_t bf[3][2];
        #pragma unroll
        for (int nt = 0; nt < 3; nt++) {
            int nb = wn * 24 + nt * 8;
            bf[nt][0] = Bs[(nb + g) * PITCH + k8 + t4    ];
            bf[nt][1] = Bs[(nb + g) * PITCH + k8 + t4 + 4];
        }
        #pragma unroll
        for (int mt = 0; mt < 2; mt++)
            #pragma unroll
            for (int nt = 0; nt < 3; nt++)
                mma_bf16(acc[mt][nt], af[mt], bf[nt]);
    }
}

__device__ __forceinline__ void stage_A96(const __nv_bfloat16* A, size_t bm, uint32_t* As, int tid) {
    for (int i = tid; i < 128 * 12; i += 256) {
        int row = i / 12, q = i - row * 12;
        ((uint4*)&As[row * PITCH])[q] = ((const uint4*)(A + (bm + row) * 96))[q];
    }
}
__device__ __forceinline__ void stage_B96(const __nv_bfloat16* Wb, int bn, uint32_t* Bs, int tid) {
    for (int i = tid; i < 96 * 12; i += 256) {
        int row = i / 12, q = i - row * 12;
        ((uint4*)&Bs[row * PITCH])[q] = ((const uint4*)(Wb + (size_t)(bn + row) * 96))[q];
    }
}

__device__ __forceinline__ void decode_tok(int r, int& b, int& d, int& h, int& w) {
    int widx = r >> 6, inner = r & 63;
    b = widx >> 11;
    int wi = widx & 2047;
    int wd = wi >> 8, wh = (wi >> 4) & 15, ww = wi & 15;
    int id = inner >> 4, ih = (inner >> 2) & 3, iw = inner & 3;
    d = (wd * 4 + id + 2) & 31;
    h = (wh * 4 + ih + 2) & 63;
    w = (ww * 4 + iw + 2) & 63;
}

// ============================================================
// K1: fused LN1 + roll + window + qkv GEMM. q output pre-scaled by 24^-0.5.
// ============================================================
__global__ void __launch_bounds__(256)
k_qkv(const float* __restrict__ x, const float* __restrict__ gw,
      const float* __restrict__ gb, const float* __restrict__ qbias)
{
    extern __shared__ char smem[];
    uint32_t* As = (uint32_t*)smem;
    uint32_t* Bs = (uint32_t*)(smem + 26624);
    float* sgw = (float*)(smem + 46592);
    float* sgb = sgw + 96;

    int tid = threadIdx.x;
    if (tid < 96) { sgw[tid] = gw[tid]; sgb[tid] = gb[tid]; }

    size_t bm = (size_t)blockIdx.x * 128;
    int t = tid & 127;
    int b, d, h, w;
    decode_tok((int)bm + t, b, d, h, w);
    size_t xbase = ((size_t)b * 96) * SP + (size_t)d * 4096 + h * 64 + w;
    int c0 = tid >> 7;

    for (int p = c0; p < 48; p += 2) {
        float v0 = x[xbase + (size_t)(2 * p) * SP];
        float v1 = x[xbase + (size_t)(2 * p + 1) * SP];
        As[t * PITCH + p] = packbf(v0, v1);
    }
    __syncthreads();

    if (tid < 128) {
        uint32_t* row = As + tid * PITCH;
        float s = 0.f, ss = 0.f;
        #pragma unroll
        for (int p = 0; p < 48; p++) {
            float2 f = unpackbf(row[p]);
            s += f.x + f.y; ss += f.x * f.x + f.y * f.y;
        }
        float mean = s * (1.f / 96.f);
        float rstd = rsqrtf(ss * (1.f / 96.f) - mean * mean + 1e-5f);
        #pragma unroll
        for (int p = 0; p < 48; p++) {
            float2 f = unpackbf(row[p]);
            f.x = (f.x - mean) * rstd * sgw[2 * p] + sgb[2 * p];
            f.y = (f.y - mean) * rstd * sgw[2 * p + 1] + sgb[2 * p + 1];
            row[p] = packbf(f.x, f.y);
        }
    }
    __syncthreads();

    int warp = tid >> 5, lane = tid & 31, g = lane >> 2, t4 = lane & 3;
    int wm = warp >> 1, wn = warp & 1;

    for (int bt = 0; bt < 3; bt++) {
        stage_B96(g_wqkv, bt * 96, Bs, tid);
        __syncthreads();
        float acc[2][6][4];
        #pragma unroll
        for (int i = 0; i < 2; i++)
            #pragma unroll
            for (int j = 0; j < 6; j++)
                #pragma unroll
                for (int r = 0; r < 4; r++) acc[i][j][r] = 0.f;
        mma_tile96(As, Bs, acc, g, t4, wm, wn);
        float scale = (bt == 0) ? 0.2041241452319315f : 1.0f;
        #pragma unroll
        for (int mt = 0; mt < 2; mt++)
            #pragma unroll
            for (int nt = 0; nt < 6; nt++) {
                int ncol = wn * 48 + nt * 8 + t4 * 2;
                #pragma unroll
                for (int half = 0; half < 2; half++) {
                    size_t row = bm + wm * 32 + mt * 16 + g + half * 8;
                    float v0 = (acc[mt][nt][half * 2 + 0] + qbias[bt * 96 + ncol]) * scale;
                    float v1 = (acc[mt][nt][half * 2 + 1] + qbias[bt * 96 + ncol + 1]) * scale;
                    *(uint32_t*)&g_qkv[row * 288 + bt * 96 + ncol] = packbf(v0, v1);
                }
            }
        __syncthreads();
    }
}

// ============================================================
// K2: tensor-core windowed attention. Bias fragments read directly
// from global (L1/L2-resident 32KB table) -> smem 55KB -> 2 blocks/SM.
// ============================================================
#define AT_QS   0
#define AT_KS   5120
#define AT_VT   10240        // bf16 view, 96 rows * 36 u32 pitch = 3456 u32
#define AT_GT   13696
#define AT_SIZE ((13696 + 64) * 4)   // 55040 B

__global__ void __launch_bounds__(512)
k_attn()
{
    extern __shared__ uint32_t sm[];
    uint32_t* Qs = sm + AT_QS;
    uint32_t* Ks = sm + AT_KS;
    uint32_t* VtU = sm + AT_VT;
    __nv_bfloat16* Vt = (__nv_bfloat16*)(sm + AT_VT);
    int* gtk = (int*)(sm + AT_GT);

    int tid = threadIdx.x;
    int bn  = blockIdx.x;
    int wi  = bn & (NWIN - 1);
    int wd = wi >> 8, wh = (wi >> 4) & 15, ww = wi & 15;
    bool interior = (wd != 7) && (wh != 15) && (ww != 15);

    const uint4* src4 = (const uint4*)(g_qkv + (size_t)bn * NWT * 288);
    const uint32_t* srcU = (const uint32_t*)src4;

    // Q/K staging + zero-pad: thread -> (sec = tid>>8, h = (tid>>6)&3, r = tid&63)
    {
        int sec = tid >> 8;
        int hq  = (tid >> 6) & 3;
        int r   = tid & 63;
        const uint4* s4 = src4 + r * 36 + sec * 12 + hq * 3;
        uint32_t* dst = (sec ? Ks : Qs) + (hq * 64 + r) * 20;
        #pragma unroll
        for (int q = 0; q < 3; q++)
            *(uint4*)(dst + q * 4) = s4[q];
        *(uint4*)(dst + 12) = make_uint4(0, 0, 0, 0);
    }
    // V transpose
    {
        int hv = tid >> 7;
        int w2 = tid & 127;
        int j  = w2 >> 1;
        int pb = (w2 & 1) * 6;
        const uint32_t* s = srcU + j * 144 + 96 + hv * 12 + pb;
        #pragma unroll
        for (int m = 0; m < 6; m++) {
            uint32_t v = s[m];
            __nv_bfloat162 bv = *reinterpret_cast<__nv_bfloat162*>(&v);
            int p = pb + m;
            Vt[(hv * 24 + 2 * p    ) * 72 + j] = bv.x;
            Vt[(hv * 24 + 2 * p + 1) * 72 + j] = bv.y;
        }
    }
    // group ids
    if (tid < 64) {
        int id = tid >> 4, ih = (tid >> 2) & 3, iw = tid & 3;
        int da = wd * 4 + id, ha = wh * 4 + ih, wa = ww * 4 + iw;
        int rd = (da < DD  - 4) ? 0 : ((da < DD  - 2) ? 1 : 2);
        int rh = (ha < HH  - 4) ? 0 : ((ha < HH  - 2) ? 1 : 2);
        int rw = (wa < WWD - 4) ? 0 : ((wa < WWD - 2) ? 1 : 2);
        gtk[tid] = rd * 9 + rh * 3 + rw;
    }
    __syncthreads();

    int w = tid >> 5, lane = tid & 31;
    int g = lane >> 2, t4 = lane & 3;
    int h  = w >> 2;          // head
    int rq = w & 3;           // 16-row slab
    const uint32_t* Qh = Qs + h * 1280;
    const uint32_t* Kh = Ks + h * 1280;

    // ---- S = Q @ K^T
    float acc[8][4];
    #pragma unroll
    for (int nt = 0; nt < 8; nt++)
        #pragma unroll
        for (int r = 0; r < 4; r++) acc[nt][r] = 0.f;

    #pragma unroll
    for (int ks = 0; ks < 2; ks++) {
        uint32_t a[4];
        a[0] = Qh[(rq * 16 + g    ) * 20 + ks * 8 + t4    ];
        a[1] = Qh[(rq * 16 + g + 8) * 20 + ks * 8 + t4    ];
        a[2] = Qh[(rq * 16 + g    ) * 20 + ks * 8 + t4 + 4];
        a[3] = Qh[(rq * 16 + g + 8) * 20 + ks * 8 + t4 + 4];
        #pragma unroll
        for (int nt = 0; nt < 8; nt++) {
            uint32_t b[2];
            b[0] = Kh[(nt * 8 + g) * 20 + ks * 8 + t4    ];
            b[1] = Kh[(nt * 8 + g) * 20 + ks * 8 + t4 + 4];
            mma_bf16(acc[nt], a, b);
        }
    }

    // ---- softmax in fragments (bias from global, unnormalized)
    int r0 = rq * 16 + g;
    int r1 = r0 + 8;
    float sum0 = 0.f, sum1 = 0.f;
    int base0 = ((h * 8 + rq * 2 + 0) * 8) * 32 + lane;
    int base1 = ((h * 8 + rq * 2 + 1) * 8) * 32 + lane;

    if (interior) {
        #pragma unroll
        for (int nt = 0; nt < 8; nt++) {
            float2 f0 = unpackbf(__ldg(&g_biasF[base0 + nt * 32]));
            float2 f1 = unpackbf(__ldg(&g_biasF[base1 + nt * 32]));
            float e0 = __expf(acc[nt][0] + f0.x);
            float e1 = __expf(acc[nt][1] + f0.y);
            float e2 = __expf(acc[nt][2] + f1.x);
            float e3 = __expf(acc[nt][3] + f1.y);
            acc[nt][0] = e0; acc[nt][1] = e1; acc[nt][2] = e2; acc[nt][3] = e3;
            sum0 += e0 + e1; sum1 += e2 + e3;
        }
    } else {
        int rg0 = gtk[r0], rg1 = gtk[r1];
        #pragma unroll
        for (int nt = 0; nt < 8; nt++) {
            int cA = nt * 8 + t4 * 2;
            int m0 = gtk[cA], m1 = gtk[cA + 1];
            float2 f0 = unpackbf(__ldg(&g_biasF[base0 + nt * 32]));
            float2 f1 = unpackbf(__ldg(&g_biasF[base1 + nt * 32]));
            float e0 = (m0 == rg0) ? __expf(acc[nt][0] + f0.x) : 0.f;
            float e1 = (m1 == rg0) ? __expf(acc[nt][1] + f0.y) : 0.f;
            float e2 = (m0 == rg1) ? __expf(acc[nt][2] + f1.x) : 0.f;
            float e3 = (m1 == rg1) ? __expf(acc[nt][3] + f1.y) : 0.f;
            acc[nt][0] = e0; acc[nt][1] = e1; acc[nt][2] = e2; acc[nt][3] = e3;
            sum0 += e0 + e1; sum1 += e2 + e3;
        }
    }
    sum0 += __shfl_xor_sync(0xffffffff, sum0, 1);
    sum0 += __shfl_xor_sync(0xffffffff, sum0, 2);
    sum1 += __shfl_xor_sync(0xffffffff, sum1, 1);
    sum1 += __shfl_xor_sync(0xffffffff, sum1, 2);
    float inv0 = 1.f / sum0;
    float inv1 = 1.f / sum1;

    // ---- O = P @ V
    float out[3][4];
    #pragma unroll
    for (int nv = 0; nv < 3; nv++)
        #pragma unroll
        for (int r = 0; r < 4; r++) out[nv][r] = 0.f;

    #pragma unroll
    for (int ksP = 0; ksP < 4; ksP++) {
        uint32_t a[4];
        a[0] = packbf(acc[2 * ksP    ][0], acc[2 * ksP    ][1]);
        a[1] = packbf(acc[2 * ksP    ][2], acc[2 * ksP    ][3]);
        a[2] = packbf(acc[2 * ksP + 1][0], acc[2 * ksP + 1][1]);
        a[3] = packbf(acc[2 * ksP + 1][2], acc[2 * ksP + 1][3]);
        #pragma unroll
        for (int nv = 0; nv < 3; nv++) {
            uint32_t b[2];
            b[0] = VtU[(h * 24 + nv * 8 + g) * 36 + ksP * 8 + t4    ];
            b[1] = VtU[(h * 24 + nv * 8 + g) * 36 + ksP * 8 + t4 + 4];
            mma_bf16(out[nv], a, b);
        }
    }

    // ---- write O
    uint32_t* attU = (uint32_t*)g_att;
    size_t tok0 = (size_t)bn * NWT + r0;
    size_t tok1 = (size_t)bn * NWT + r1;
    #pragma unroll
    for (int nv = 0; nv < 3; nv++) {
        int col = h * 24 + nv * 8 + t4 * 2;
        attU[(tok0 * 96 + col) >> 1] = packbf(out[nv][0] * inv0, out[nv][1] * inv0);
        attU[(tok1 * 96 + col) >> 1] = packbf(out[nv][2] * inv1, out[nv][3] * inv1);
    }
}

// ============================================================
// K3: proj GEMM + window reverse + roll + residual + LN2
// ============================================================
__global__ void __launch_bounds__(256)
k_proj(const float* __restrict__ x, const float* __restrict__ pbias,
       const float* __restrict__ g2, const float* __restrict__ b2)
{
    extern __shared__ char smem[];
    uint32_t* As = (uint32_t*)smem;
    uint32_t* Bs = (uint32_t*)(smem + 26624);
    float* xs    = (float*)smem;
    int*   sprow = (int*)(smem + 49664);
    float* smu   = (float*)(smem + 50176);
    float* srs   = (float*)(smem + 50688);
    float* sg2   = (float*)(smem + 51200);
    float* sb2   = (float*)(smem + 51584);

    int tid = threadIdx.x;
    if (tid < 96) { sg2[tid] = g2[tid]; sb2[tid] = b2[tid]; }

    size_t bm = (size_t)blockIdx.x * 128;
    stage_A96(g_att, bm, As, tid);
    stage_B96(g_wproj, 0, Bs, tid);
    __syncthreads();

    int warp = tid >> 5, lane = tid & 31, g = lane >> 2, t4 = lane & 3;
    int wm = warp >> 1, wn = warp & 1;

    float acc[2][6][4];
    #pragma unroll
    for (int i = 0; i < 2; i++)
        #pragma unroll
        for (int j = 0; j < 6; j++)
            #pragma unroll
            for (int r = 0; r < 4; r++) acc[i][j][r] = 0.f;
    mma_tile96(As, Bs, acc, g, t4, wm, wn);
    __syncthreads();

    #pragma unroll
    for (int mt = 0; mt < 2; mt++)
        #pragma unroll
        for (int nt = 0; nt < 6; nt++) {
            int cl = wn * 48 + nt * 8 + t4 * 2;
            #pragma unroll
            for (int half = 0; half < 2; half++) {
                int rl = wm * 32 + mt * 16 + g + half * 8;
                xs[rl * 97 + cl    ] = acc[mt][nt][half * 2 + 0] + pbias[cl];
                xs[rl * 97 + cl + 1] = acc[mt][nt][half * 2 + 1] + pbias[cl + 1];
            }
        }
    __syncthreads();

    int t = tid & 127;
    int b, d, h, w;
    decode_tok((int)bm + t, b, d, h, w);
    int spoff = d * 4096 + h * 64 + w;
    size_t xbase = ((size_t)b * 96) * SP + spoff;
    if (tid < 128) sprow[tid] = b * SP + spoff;
    int c0 = tid >> 7;
    for (int c = c0; c < 96; c += 2)
        xs[t * 97 + c] += x[xbase + (size_t)c * SP];
    __syncthreads();

    if (tid < 128) {
        const float* row = xs + tid * 97;
        float s = 0.f, ss = 0.f;
        #pragma unroll
        for (int c = 0; c < 96; c++) { float v = row[c]; s += v; ss += v * v; }
        float mean = s * (1.f / 96.f);
        smu[tid] = mean;
        srs[tid] = rsqrtf(ss * (1.f / 96.f) - mean * mean + 1e-5f);
    }
    __syncthreads();

    #pragma unroll
    for (int tk = 0; tk < 16; tk++) {
        int tt = warp * 16 + tk;
        size_t row = (size_t)sprow[tt] * 96;
        float mu = smu[tt], rs = srs[tt];
        #pragma unroll
        for (int rep = 0; rep < 3; rep++) {
            int c = lane + rep * 32;
            float v = xs[tt * 97 + c];
            g_x2[row + c] = v;
            g_hn[row + c] = __float2bfloat16_rn((v - mu) * rs * sg2[c] + sb2[c]);
        }
    }
}

// ============================================================
// K4: fused MLP, M=128, 512 threads, pipelined per-chunk:
// fc1 chunk bt -> GELU -> single m1 buffer -> fc2 K-chunk bt accumulate.
// smem 93KB -> 2 blocks/SM.
// ============================================================
#define MLPB_B1  26624
#define MLPB_B2  46592
#define MLPB_M1  66560
#define MLP_SIZE 93184

__global__ void __launch_bounds__(512)
k_mlp(const float* __restrict__ f1bias, const float* __restrict__ f2bias,
      float* __restrict__ out)
{
    extern __shared__ char smem[];
    uint32_t* As   = (uint32_t*)smem;
    uint32_t* B1   = (uint32_t*)(smem + MLPB_B1);
    uint32_t* B2   = (uint32_t*)(smem + MLPB_B2);
    uint32_t* M1   = (uint32_t*)(smem + MLPB_M1);
    float*    sout = (float*)smem;    // reuse As region in epilogue

    int tid = threadIdx.x;
    size_t bm = (size_t)blockIdx.x * 128;
    int warp = tid >> 5, lane = tid & 31, g = lane >> 2, t4 = lane & 3;
    int wm = warp >> 2;     // 0..3: 32-row slab
    int wn = warp & 3;      // 0..3: 24-col slab

    // stage A (g_hn): thread -> row = tid>>2, q = (tid&3)*3 + m
    {
        int rowA = tid >> 2;
        int qb = (tid & 3) * 3;
        const uint4* sA = (const uint4*)(g_hn + (bm + rowA) * 96) + qb;
        uint4* dA = (uint4*)&As[rowA * PITCH] + qb;
        dA[0] = sA[0]; dA[1] = sA[1]; dA[2] = sA[2];
    }

    float acc2[2][3][4];
    #pragma unroll
    for (int i = 0; i < 2; i++)
        #pragma unroll
        for (int j = 0; j < 3; j++)
            #pragma unroll
            for (int r = 0; r < 4; r++) acc2[i][j][r] = 0.f;

    for (int bt = 0; bt < 4; bt++) {
        // stage both weight chunks
        if (tid < 384) {
            int row = tid >> 2;
            int qb = (tid & 3) * 3;
            const uint4* s1 = (const uint4*)(g_wfc1 + (size_t)(bt * 96 + row) * 96) + qb;
            uint4* d1 = (uint4*)&B1[row * PITCH] + qb;
            d1[0] = s1[0]; d1[1] = s1[1]; d1[2] = s1[2];
            const uint4* s2 = (const uint4*)(g_wfc2 + (size_t)row * 384 + bt * 96) + qb;
            uint4* d2 = (uint4*)&B2[row * PITCH] + qb;
            d2[0] = s2[0]; d2[1] = s2[1]; d2[2] = s2[2];
        }
        __syncthreads();   // A + B1 + B2 ready; previous fc2 mma done reading M1/B2

        // fc1 chunk
        float acc[2][3][4];
        #pragma unroll
        for (int i = 0; i < 2; i++)
            #pragma unroll
            for (int j = 0; j < 3; j++)
                #pragma unroll
                for (int r = 0; r < 4; r++) acc[i][j][r] = 0.f;
        mma_tile96_w16(As, B1, acc, g, t4, wm, wn);

        #pragma unroll
        for (int mt = 0; mt < 2; mt++)
            #pragma unroll
            for (int nt = 0; nt < 3; nt++) {
                int ncol = wn * 24 + nt * 8 + t4 * 2;
                #pragma unroll
                for (int half = 0; half < 2; half++) {
                    int row = wm * 32 + mt * 16 + g + half * 8;
                    float v0 = acc[mt][nt][half * 2 + 0] + f1bias[bt * 96 + ncol];
                    float v1 = acc[mt][nt][half * 2 + 1] + f1bias[bt * 96 + ncol + 1];
                    v0 = 0.5f * v0 * (1.f + erff(v0 * 0.70710678118654752f));
                    v1 = 0.5f * v1 * (1.f + erff(v1 * 0.70710678118654752f));
                    M1[row * PITCH + (ncol >> 1)] = packbf(v0, v1);
                }
            }
        __syncthreads();   // M1 complete

        // fc2 accumulate from M1 x B2
        mma_tile96_w16(M1, B2, acc2, g, t4, wm, wn);
        __syncthreads();   // protect B1/B2/M1 before next stage
    }

    // ---- epilogue: + bias + x2 residual, transpose to channel-major out
    int b   = (int)(bm >> 17);
    int sp0 = (int)(bm & (SP - 1));

    #pragma unroll
    for (int p = 0; p < 2; p++) {
        if ((wn >> 1) == p) {
            #pragma unroll
            for (int mt = 0; mt < 2; mt++)
                #pragma unroll
                for (int nt = 0; nt < 3; nt++) {
                    int cl = (wn & 1) * 24 + nt * 8 + t4 * 2;   // 0..47
                    #pragma unroll
                    for (int half = 0; half < 2; half++) {
                        int rl = wm * 32 + mt * 16 + g + half * 8;
                        float2 xv = *(const float2*)&g_x2[(bm + rl) * 96 + p * 48 + cl];
                        sout[(cl    ) * 132 + rl] = acc2[mt][nt][half * 2 + 0] + f2bias[p * 48 + cl    ] + xv.x;
                        sout[(cl + 1) * 132 + rl] = acc2[mt][nt][half * 2 + 1] + f2bias[p * 48 + cl + 1] + xv.y;
                    }
                }
        }
        __syncthreads();
        for (int i = tid; i < 48 * 128; i += 512) {
            int c = i >> 7, tk = i & 127;
            out[((size_t)b * 96 + p * 48 + c) * SP + sp0 + tk] = sout[c * 132 + tk];
        }
        __syncthreads();
    }
}

// ============================================================
// launch
// ============================================================
extern "C" void kernel_launch(void* const* d_in, const int* in_sizes, int n_in,
                              void* d_out, int out_size)
{
    const float* x    = (const float*)d_in[0];
    const float* n1g  = (const float*)d_in[1];
    const float* n1b  = (const float*)d_in[2];
    const float* qkvw = (const float*)d_in[3];
    const float* qkvb = (const float*)d_in[4];
    const float* rpb  = (const float*)d_in[5];
    const float* pw   = (const float*)d_in[6];
    const float* pb   = (const float*)d_in[7];
    const float* n2g  = (const float*)d_in[8];
    const float* n2b  = (const float*)d_in[9];
    const float* f1w  = (const float*)d_in[10];
    const float* f1b  = (const float*)d_in[11];
    const float* f2w  = (const float*)d_in[12];
    const float* f2b  = (const float*)d_in[13];
    float* out = (float*)d_out;

    static int smem_set = 0;
    if (!smem_set) {
        cudaFuncSetAttribute(k_qkv,  cudaFuncAttributeMaxDynamicSharedMemorySize, 48 * 1024);
        cudaFuncSetAttribute(k_attn, cudaFuncAttributeMaxDynamicSharedMemorySize, AT_SIZE);
        cudaFuncSetAttribute(k_proj, cudaFuncAttributeMaxDynamicSharedMemorySize, 52 * 1024);
        cudaFuncSetAttribute(k_mlp,  cudaFuncAttributeMaxDynamicSharedMemorySize, MLP_SIZE);
        smem_set = 1;
    }

    const int SZ_QKV  = 46592 + 768;
    const int SZ_PROJ = 51968;

    k_wconv<<<432, 256>>>(qkvw, pw, f1w, f2w);
    k_bias <<<32, 256>>>(rpb);
    k_qkv <<<NTOK / 128, 256, SZ_QKV >>>(x, n1g, n1b, qkvb);
    k_attn<<<BATCH * NWIN, 512, AT_SIZE>>>();
    k_proj<<<NTOK / 128, 256, SZ_PROJ>>>(x, pb, n2g, n2b);
    k_mlp <<<NTOK / 128, 512, MLP_SIZE>>>(f1b, f2b, out);
}